// round 9
// baseline (speedup 1.0000x reference)
#include <cuda_runtime.h>
#include <cstdint>

// Fixed shapes: B=1, N=64, X=256, Y=256, Z=32
#define NINST 64
#define V (256*256*32)           // 2,097,152 floats / instance
#define CVOX 128                 // voxels per chunk per instance
#define CW 4                     // packed words per chunk per instance
#define NCHUNK (V/CVOX)          // 16384 chunks
#define NTHR 256
#define NBLK 444                 // 148 SMs * 3 resident blocks
#define NSLOT 8                  // partial accumulator slots

// Device state (zero-initialized at load; the last block of every launch
// restores it to zero, so graph replays start clean).
__device__ unsigned g_partial[NSLOT * NINST * NINST];
__device__ unsigned g_score[NSLOT * NINST];
__device__ unsigned g_done;

// ---------------------------------------------------------------------------
// Single fused kernel, warp-autonomous loading.
//   Warp wp owns instances [8wp, 8wp+8). Per chunk c (128 voxels):
//     - 8 independent LDG.128 (one 512B slice per instance), ballot-pack to
//       4 words each, write own packed[] columns  (no cross-warp coupling)
//     - one __syncthreads, then triangular pairwise popcount (240 units)
//   packed[] is ping-pong buffered so no trailing barrier is needed.
// Last block reduces partials, runs exact-integer NMS, resets state.
// ---------------------------------------------------------------------------
__global__ __launch_bounds__(NTHR, 3) void fused_nms_kernel(
    const float* __restrict__ mask, float* __restrict__ out)
{
    __shared__ unsigned packed[2][CW][NINST];    // 2 KB ping-pong
    __shared__ unsigned inter[NINST * NINST];    // 16 KB (tail; dead in main)
    __shared__ unsigned ssc[NINST];
    __shared__ int s_done;

    const int tid  = threadIdx.x;
    const int lane = tid & 31;
    const int wp   = tid >> 5;                   // 8 warps
    const int binst = wp * 8;                    // first owned instance

    // ----- triangular work-unit decode (threads 0..239) -----
    // unit = (off-diag 4x4 tile k, word-half h) -> words {2h, 2h+1}
    int i0 = 0, j0 = 4, w0 = 0;
    if (tid < 240) {
        int k = tid >> 1;
        int a = 0, rem = k;
        while (rem >= 15 - a) { rem -= 15 - a; a++; }
        i0 = a * 4; j0 = (a + 1 + rem) * 4;
        w0 = (tid & 1) * 2;
    }

    unsigned acc[4][4];
#pragma unroll
    for (int r = 0; r < 4; r++)
#pragma unroll
        for (int c2 = 0; c2 < 4; c2++) acc[r][c2] = 0u;
    unsigned sc = 0;   // score for instance binst+lane (lanes 0..7)

    // Static chunk range for this block.
    const int c0 = (int)(((long long)blockIdx.x * NCHUNK) / NBLK);
    const int c1 = (int)(((long long)(blockIdx.x + 1) * NCHUNK) / NBLK);

    // Per-lane gmem base: instance (binst+jj), voxel lane*4 within chunk.
    const unsigned* mbase =
        (const unsigned*)mask + (size_t)binst * V + (size_t)lane * 4;

    // Preload chunk c0 (8 independent 16B loads, MLP=8).
    uint4 v[8];
#pragma unroll
    for (int jj = 0; jj < 8; jj++)
        v[jj] = __ldg((const uint4*)(mbase + (size_t)jj * V + (size_t)c0 * CVOX));

    for (int c = c0; c < c1; c++) {
        const int buf = c & 1;

        // ---- pack own 8 instances (fixed voxel permutation, identical for
        // all instances -> pairwise popcounts and scores unaffected) ----
#pragma unroll
        for (int jj = 0; jj < 8; jj++) {
            unsigned b0 = __ballot_sync(0xffffffffu, v[jj].x != 0u);
            unsigned b1 = __ballot_sync(0xffffffffu, v[jj].y != 0u);
            unsigned b2 = __ballot_sync(0xffffffffu, v[jj].z != 0u);
            unsigned b3 = __ballot_sync(0xffffffffu, v[jj].w != 0u);
            if (lane == jj) {
                packed[buf][0][binst + jj] = b0;
                packed[buf][1][binst + jj] = b1;
                packed[buf][2][binst + jj] = b2;
                packed[buf][3][binst + jj] = b3;
                sc += __popc(b0) + __popc(b1) + __popc(b2) + __popc(b3);
            }
        }

        // ---- prefetch chunk c+1 (latency hidden by sync + phase B) ----
        if (c + 1 < c1) {
            const unsigned* p = mbase + (size_t)(c + 1) * CVOX;
#pragma unroll
            for (int jj = 0; jj < 8; jj++)
                v[jj] = __ldg((const uint4*)(p + (size_t)jj * V));
        }

        __syncthreads();   // all packed[buf] columns visible

        // ---- phase B: 2 words on this thread's upper-triangle tile ----
        if (tid < 240) {
            uint4 A0 = *(const uint4*)&packed[buf][w0][i0];
            uint4 B0 = *(const uint4*)&packed[buf][w0][j0];
            uint4 A1 = *(const uint4*)&packed[buf][w0 + 1][i0];
            uint4 B1 = *(const uint4*)&packed[buf][w0 + 1][j0];
            unsigned a0[4] = {A0.x, A0.y, A0.z, A0.w};
            unsigned b0[4] = {B0.x, B0.y, B0.z, B0.w};
            unsigned a1[4] = {A1.x, A1.y, A1.z, A1.w};
            unsigned b1[4] = {B1.x, B1.y, B1.z, B1.w};
#pragma unroll
            for (int r = 0; r < 4; r++)
#pragma unroll
                for (int c2 = 0; c2 < 4; c2++)
                    acc[r][c2] +=
                        __popc(a0[r] & b0[c2]) + __popc(a1[r] & b1[c2]);
        }
        // no trailing barrier: next pack writes packed[buf^1]; a write to
        // packed[buf] can only happen after sync(c+1), which every warp
        // reaches only after finishing phase B(c).
    }

    // ---- flush per-block totals ----
    {
        unsigned* gp =
            g_partial + (unsigned)(blockIdx.x & (NSLOT - 1)) * (NINST * NINST);
        if (tid < 240) {
#pragma unroll
            for (int r = 0; r < 4; r++)
#pragma unroll
                for (int c2 = 0; c2 < 4; c2++)
                    atomicAdd(&gp[(i0 + r) * NINST + (j0 + c2)], acc[r][c2]);
        }
        if (lane < 8) {
            unsigned* gs =
                g_score + (unsigned)(blockIdx.x & (NSLOT - 1)) * NINST;
            atomicAdd(&gs[binst + lane], sc);
        }
    }
    __threadfence();
    __syncthreads();
    if (tid == 0) s_done = (int)atomicAdd(&g_done, 1u);
    __syncthreads();
    if (s_done != NBLK - 1) return;

    // ------------------- Last block: reduce + NMS + reset -------------------
    {   // vectorized reduce of NSLOT slots (L1-bypassing loads)
        const uint4* gp4 = (const uint4*)g_partial;   // [NSLOT][1024] uint4
        uint4* in4 = (uint4*)inter;
        for (int e = tid; e < (NINST * NINST) / 4; e += NTHR) {
            uint4 s = make_uint4(0u, 0u, 0u, 0u);
#pragma unroll
            for (int k = 0; k < NSLOT; k++) {
                uint4 w = __ldcg(&gp4[k * (NINST * NINST / 4) + e]);
                s.x += w.x; s.y += w.y; s.z += w.z; s.w += w.w;
            }
            in4[e] = s;
        }
        if (tid < NINST) {
            unsigned s = 0;
#pragma unroll
            for (int k = 0; k < NSLOT; k++)
                s += __ldcg(&g_score[k * NINST + tid]);
            ssc[tid] = s;
        }
    }
    __syncthreads();

    {   // symmetrize: lower-triangle tiles were never written (zeros) ->
        // copy the upper value down via max. Diagonal stays 0 (harmless:
        // j==i gives hit=false below).
        for (int e = tid; e < NINST * NINST; e += NTHR) {
            int i = e >> 6, j = e & 63;
            if (i > j) {
                unsigned hi = inter[j * NINST + i];
                unsigned lo = inter[e];
                inter[e] = hi > lo ? hi : lo;
            }
        }
    }

    {   // reset device state for the next replay
        uint4 z = make_uint4(0u, 0u, 0u, 0u);
        uint4* gz = (uint4*)g_partial;
        for (int e = tid; e < (NSLOT * NINST * NINST) / 4; e += NTHR) gz[e] = z;
        if (tid < NSLOT * NINST) g_score[tid] = 0u;
        if (tid == 0) g_done = 0u;
    }
    __syncthreads();

    if (tid < 32) {
        const unsigned sj0 = ssc[lane];
        const unsigned sj1 = ssc[lane + 32];
        unsigned long long ind = ~0ULL;

        for (int i = 0; i < NINST; i++) {
            if (!((ind >> i) & 1ULL)) continue;  // warp-uniform
            const unsigned si  = ssc[i];
            const unsigned in0 = inter[i * NINST + lane];
            const unsigned in1 = inter[i * NINST + lane + 32];
            // iou > 0.5 <=> 2*inter > union (exact integers; counts < 2^23)
            const bool h0 = (2u * in0 > si + sj0 - in0);
            const bool h1 = (2u * in1 > si + sj1 - in1);
            unsigned a0 = __ballot_sync(0xffffffffu, h0 && (si > sj0));
            unsigned a1 = __ballot_sync(0xffffffffu, h1 && (si > sj1));
            unsigned c0m = __ballot_sync(0xffffffffu, h0 && (sj0 > si));
            unsigned c1m = __ballot_sync(0xffffffffu, h1 && (sj1 > si));
            unsigned long long A  = ((unsigned long long)a1 << 32) | a0;
            unsigned long long Bm = ((unsigned long long)c1m << 32) | c0m;
            if (A) {
                int jb = __ffsll((long long)A) - 1;   // first break j
                unsigned long long before = (1ULL << jb) - 1ULL;
                if (Bm & before) ind &= ~(1ULL << i); // earlier j beat i first
                ind &= ~(1ULL << jb);
            } else if (Bm) {
                ind &= ~(1ULL << i);
            }
        }
        out[lane]      = (float)((ind >> lane) & 1ULL);
        out[lane + 32] = (float)((ind >> (lane + 32)) & 1ULL);
    }
}

// ---------------------------------------------------------------------------
extern "C" void kernel_launch(void* const* d_in, const int* in_sizes, int n_in,
                              void* d_out, int out_size) {
    const float* mask = (const float*)d_in[0];
    fused_nms_kernel<<<NBLK, NTHR>>>(mask, (float*)d_out);
}